// round 1
// baseline (speedup 1.0000x reference)
#include <cuda_runtime.h>
#include <cuda_bf16.h>
#include <cstdint>

#define K_TAGS 256
#define N_BATCH 64
#define T_SEQ 512

// ---- shared memory layout (bytes) ----
// P^T bf16 swizzled: rows j (owned column), 512 B/row
#define OFF_P      0
#define OFF_A      131072              // a_sh[2][256] float (double buffered)
#define OFF_REDS   133120              // red_s[2] float: broadcast normalizer M
#define OFF_RED8   133152              // float2 red8[8]: per-warp reduction slots
#define OFF_JTOT   133248              // 1 float: joint total
#define OFF_MASK   133264              // pad to 16 -> mask row starts 133264? keep aligned:
#define OFF_MASKR  133280              // 512 floats
#define OFF_TAGSR  135328              // 512 ints
#define SMEM_BYTES 137376

__device__ float g_partial[N_BATCH];

__device__ __forceinline__ float bflo(unsigned u) { return __uint_as_float(u << 16); }
__device__ __forceinline__ float bfhi(unsigned u) { return __uint_as_float(u & 0xffff0000u); }

__global__ void __launch_bounds__(256, 1)
crf_kernel(const float* __restrict__ logits,
           const int*   __restrict__ tags,
           const int*   __restrict__ mask,
           const float* __restrict__ transitions)
{
    extern __shared__ char smem[];
    float*  a_base  = (float*) (smem + OFF_A);
    float*  red_s   = (float*) (smem + OFF_REDS);
    float2* red8    = (float2*)(smem + OFF_RED8);
    float*  jtot_s  = (float*) (smem + OFF_JTOT);
    float*  mask_sh = (float*) (smem + OFF_MASKR);
    int*    tags_sh = (int*)   (smem + OFF_TAGSR);

    const int b = blockIdx.x;
    const int j = threadIdx.x;
    const unsigned base_bt = (unsigned)b * T_SEQ * K_TAGS;

    // ---- stage tags / mask rows ----
    for (int t = j; t < T_SEQ; t += 256) {
        tags_sh[t] = tags[b * T_SEQ + t];
        mask_sh[t] = (float)mask[b * T_SEQ + t];
    }

    // ---- build P^T[j][i] = exp(trans[i][j]) as bf16, XOR-swizzled ----
    // chunk c = i>>3 stored at 16B slot (c ^ (j&7)) within row j.
    #pragma unroll 4
    for (int i = 0; i < K_TAGS; i++) {
        float tv = transitions[i * K_TAGS + j];          // coalesced
        __nv_bfloat16 pb = __float2bfloat16(__expf(tv));
        unsigned off = (unsigned)j * 512u
                     + (unsigned)(((i >> 3) ^ (j & 7)) << 4)
                     + (unsigned)((i & 7) * 2);
        *(__nv_bfloat16*)(smem + off) = pb;
    }
    __syncthreads();

    // ---- joint likelihood (cheap, done up front) ----
    float jloc = 0.f, msloc = 0.f;
    for (int t = j; t < T_SEQ; t += 256) {
        float mt = mask_sh[t];
        int   tg = tags_sh[t];
        if (t < T_SEQ - 1)
            jloc += logits[base_bt + (unsigned)t * K_TAGS + tg] * mt;   // emit
        if (t >= 1)
            jloc += transitions[tags_sh[t - 1] * K_TAGS + tg] * mt;     // transition
        msloc += mt;
    }
    #pragma unroll
    for (int o = 16; o; o >>= 1) {
        jloc  += __shfl_xor_sync(0xffffffffu, jloc,  o);
        msloc += __shfl_xor_sync(0xffffffffu, msloc, o);
    }
    if ((j & 31) == 0) red8[j >> 5] = make_float2(jloc, msloc);
    __syncthreads();
    if (j == 0) {
        float js = 0.f, ms = 0.f;
        #pragma unroll
        for (int w = 0; w < 8; w++) { js += red8[w].x; ms += red8[w].y; }
        int last_idx = (int)ms - 1;
        if (last_idx < 0) last_idx = 0;
        if (last_idx > T_SEQ - 1) last_idx = T_SEQ - 1;
        int ltag = tags_sh[last_idx];
        js += logits[base_bt + (unsigned)(T_SEQ - 1) * K_TAGS + ltag] * mask_sh[T_SEQ - 1];
        *jtot_s = js;
    }

    // ---- forward recursion ----
    float alpha = logits[base_bt + j];          // alpha0 = logits[b,0,:]
    if (j == 0) red_s[0] = alpha;               // normalizer seed (any value near max is exact)
    __syncthreads();

    const unsigned pbase = (unsigned)j * 512u + ((unsigned)(j & 7) << 4);

    for (int t = 1; t < T_SEQ; t++) {
        const int buf = t & 1;
        float lg   = logits[base_bt + (unsigned)t * K_TAGS + j];   // issued early, hidden by matvec
        float mval = mask_sh[t];
        float M    = red_s[(t - 1) & 1];

        a_base[buf * 256 + j] = __expf(alpha - M);
        __syncthreads();

        const float4* av = (const float4*)(smem + OFF_A + buf * 1024);
        float acc0 = 0.f, acc1 = 0.f, acc2 = 0.f, acc3 = 0.f;
        float acc4 = 0.f, acc5 = 0.f, acc6 = 0.f, acc7 = 0.f;
        #pragma unroll
        for (int c = 0; c < 32; c++) {
            uint4  p = *(const uint4*)(smem + (pbase ^ (unsigned)(c << 4)));
            float4 x = av[2 * c];
            float4 y = av[2 * c + 1];
            acc0 = fmaf(x.x, bflo(p.x), acc0);
            acc1 = fmaf(x.y, bfhi(p.x), acc1);
            acc2 = fmaf(x.z, bflo(p.y), acc2);
            acc3 = fmaf(x.w, bfhi(p.y), acc3);
            acc4 = fmaf(y.x, bflo(p.z), acc4);
            acc5 = fmaf(y.y, bfhi(p.z), acc5);
            acc6 = fmaf(y.z, bflo(p.w), acc6);
            acc7 = fmaf(y.w, bfhi(p.w), acc7);
        }
        float acc = ((acc0 + acc1) + (acc2 + acc3)) + ((acc4 + acc5) + (acc6 + acc7));

        float nalpha = M + __logf(acc) + lg;
        alpha = (mval != 0.f) ? nalpha : alpha;

        if (j == 0) red_s[buf] = alpha;         // normalizer for next step
        __syncthreads();
    }

    // ---- final logsumexp (denominator) ----
    float M = red_s[(T_SEQ - 1) & 1];
    float e = __expf(alpha - M);
    #pragma unroll
    for (int o = 16; o; o >>= 1) e += __shfl_xor_sync(0xffffffffu, e, o);
    if ((j & 31) == 0) red8[j >> 5].x = e;
    __syncthreads();
    if (j == 0) {
        float s = 0.f;
        #pragma unroll
        for (int w = 0; w < 8; w++) s += red8[w].x;
        float den = M + __logf(s);
        g_partial[b] = *jtot_s - den;
    }
}

__global__ void crf_finalize(float* __restrict__ out)
{
    if (threadIdx.x == 0) {
        float s = 0.f;
        #pragma unroll
        for (int b = 0; b < N_BATCH; b++) s += g_partial[b];   // fixed order: deterministic
        out[0] = s;
    }
}

extern "C" void kernel_launch(void* const* d_in, const int* in_sizes, int n_in,
                              void* d_out, int out_size)
{
    (void)in_sizes; (void)n_in; (void)out_size;
    const float* logits      = (const float*)d_in[0];
    const int*   tags        = (const int*)  d_in[1];
    const int*   mask        = (const int*)  d_in[2];
    const float* transitions = (const float*)d_in[3];

    cudaFuncSetAttribute(crf_kernel,
                         cudaFuncAttributeMaxDynamicSharedMemorySize, SMEM_BYTES);
    crf_kernel<<<N_BATCH, 256, SMEM_BYTES>>>(logits, tags, mask, transitions);
    crf_finalize<<<1, 32>>>((float*)d_out);
}